// round 7
// baseline (speedup 1.0000x reference)
#include <cuda_runtime.h>
#include <math.h>
#include <stdint.h>

#define B_  128
#define T_  1024
#define NX_ 256
#define NH_ 512
#define NY_ 256

// Persistent state (allocation-free scratch).
__device__ float g_h[2][B_ * NH_];
// Per-domain barriers: domain = (bt, group), 16 CTAs each. Padded to 128B.
__device__ unsigned g_cnt[8][2][32];
__device__ unsigned g_gen[8][2][32];
__device__ unsigned g_fin_cnt[8][32];
__device__ unsigned g_fin_gen[8][32];

// ---------------------------------------------------------------------------
// Generic NT SGEMM (proven): C[m][n] = sum_k A[m][k] * B[n][k]
// ---------------------------------------------------------------------------
template <int BM, int BN, int BK, int TM, int TN, int NT>
__global__ __launch_bounds__(NT) void sgemm_nt(
    const float* __restrict__ A,
    const float* __restrict__ Bm,
    float* __restrict__ C,
    int M, int N, int K)
{
    __shared__ float As[BK][BM];
    __shared__ float Bs[BK][BN];

    const int tid = threadIdx.x;
    const int m0 = blockIdx.y * BM;
    const int n0 = blockIdx.x * BN;
    const int tx = tid % (BN / TN);
    const int ty = tid / (BN / TN);

    float acc[TM][TN];
#pragma unroll
    for (int i = 0; i < TM; i++)
#pragma unroll
        for (int j = 0; j < TN; j++) acc[i][j] = 0.0f;

    for (int k0 = 0; k0 < K; k0 += BK) {
#pragma unroll
        for (int i = tid; i < BM * (BK / 4); i += NT) {
            int m = i / (BK / 4);
            int kq = (i % (BK / 4)) * 4;
            float4 v = *(const float4*)(A + (long)(m0 + m) * K + k0 + kq);
            As[kq + 0][m] = v.x;
            As[kq + 1][m] = v.y;
            As[kq + 2][m] = v.z;
            As[kq + 3][m] = v.w;
        }
#pragma unroll
        for (int i = tid; i < BN * (BK / 4); i += NT) {
            int n = i / (BK / 4);
            int kq = (i % (BK / 4)) * 4;
            float4 v = *(const float4*)(Bm + (long)(n0 + n) * K + k0 + kq);
            Bs[kq + 0][n] = v.x;
            Bs[kq + 1][n] = v.y;
            Bs[kq + 2][n] = v.z;
            Bs[kq + 3][n] = v.w;
        }
        __syncthreads();

#pragma unroll
        for (int k = 0; k < BK; ++k) {
            float a[TM], b[TN];
#pragma unroll
            for (int i = 0; i < TM; i++) a[i] = As[k][ty * TM + i];
#pragma unroll
            for (int j = 0; j < TN; j++) b[j] = Bs[k][tx * TN + j];
#pragma unroll
            for (int i = 0; i < TM; i++)
#pragma unroll
                for (int j = 0; j < TN; j++) acc[i][j] = fmaf(a[i], b[j], acc[i][j]);
        }
        __syncthreads();
    }

#pragma unroll
    for (int i = 0; i < TM; i++) {
        float4 v = make_float4(acc[i][0], acc[i][1], acc[i][2], acc[i][3]);
        *(float4*)(C + (long)(m0 + ty * TM + i) * N + n0 + tx * TN) = v;
    }
}

// ---------------------------------------------------------------------------
// Helpers
// ---------------------------------------------------------------------------
__device__ __forceinline__ void ffma2(unsigned long long& d,
                                      unsigned long long a, unsigned long long b)
{
    asm("fma.rn.f32x2 %0, %1, %2, %0;" : "+l"(d) : "l"(a), "l"(b));
}
// Named barrier over one group's 256 threads (barrier id = gid+1).
__device__ __forceinline__ void bar_group(int gid)
{
    asm volatile("bar.sync %0, 256;" :: "r"(gid + 1) : "memory");
}

// ---------------------------------------------------------------------------
// Fused persistent kernel, two overlapped batch-groups per CTA.
// Grid = 128 CTAs = 8 bt x 16 jt. 512 threads = 2 groups x 8 warps.
// Group g of CTA(bt,jt): batches bt*16 + g*8 ..+8, output cols jt*32..+32.
// Sync domain = the 16 CTAs sharing (bt,g): global count/gen barrier.
// SMEM: whT[512][32] 64KB (shared) | hTd[g][512][16] dup-pairs 32KB x2 |
//       red[g][8][256] 8KB x2  => 144KB.
// ---------------------------------------------------------------------------
#define NTHR     512
#define DOM_SZ   16

#define WHT_OFF  0
#define HTD_OFF  16384
#define RED_OFF  32768
#define SMEM_FLOATS (RED_OFF + 2 * 2048)
#define SMEM_BYTES  (SMEM_FLOATS * 4)   // 147456

__device__ __forceinline__ void domain_sync(int bt, int gid, int tidg)
{
    __threadfence();
    bar_group(gid);
    if (tidg == 0) {
        volatile unsigned* genp = &g_gen[bt][gid][0];
        unsigned gen = *genp;
        unsigned c = atomicAdd(&g_cnt[bt][gid][0], 1u);
        if (c == DOM_SZ - 1) {
            g_cnt[bt][gid][0] = 0;
            __threadfence();
            atomicExch(&g_gen[bt][gid][0], gen + 1);
        } else {
            while (*genp == gen) { __nanosleep(32); }
        }
    }
    bar_group(gid);
}

__global__ __launch_bounds__(NTHR, 1) void rnn_fused2(
    const float* __restrict__ Wh,   // [NH][NH]
    const float* __restrict__ h0,   // [B][NH]
    const float* __restrict__ Wy,   // [NY][NH]
    float* __restrict__ hs,         // [B][T][NH] (pre in, h out in place)
    float* __restrict__ y)          // [B][T][NY]
{
    extern __shared__ float sm[];
    float* whT = sm + WHT_OFF;   // [k][j] stride 32

    const int tid  = threadIdx.x;
    const int lane = tid & 31;
    const int gid  = tid >> 8;          // group 0/1
    const int tidg = tid & 255;         // tid within group
    const int widg = (tid >> 5) & 7;    // warp within group

    const int jt  = blockIdx.x & 15;
    const int bt  = blockIdx.x >> 4;
    const int j0g = jt * 32;
    const int b0  = bt * 16 + gid * 8;  // this group's 8 batches

    float* hTd = sm + HTD_OFF + gid * 8192;  // [k][b*2] stride 16, dup pairs
    float* red = sm + RED_OFF + gid * 2048;  // [w][b*32+j]

    // ---- resident Wh tile (shared by both groups): whT[k][j] ----
    for (int i = tid; i < 32 * 128; i += NTHR) {
        int j  = i >> 7;
        int kq = (i & 127) * 4;
        float4 v = *(const float4*)(Wh + (size_t)(j0g + j) * NH_ + kq);
        whT[(kq + 0) * 32 + j] = v.x;
        whT[(kq + 1) * 32 + j] = v.y;
        whT[(kq + 2) * 32 + j] = v.z;
        whT[(kq + 3) * 32 + j] = v.w;
    }
    __syncthreads();

    // compute mapping: 8 warps k-split 64 each; lane tile = 2b x 4j
    const int bg  = lane >> 3;       // batch pair group: batches bg*2..+1
    const int jg  = lane & 7;        // col group: cols jg*4..+3
    const int kw0 = widg * 64;

    // reload mapping: rb = tidg&7, 4 float4 per thread
    const int rb  = tidg & 7;
    const int rrow = tidg >> 3;      // 0..31

    // epilogue mapping: one output per thread
    const int eb = tidg >> 5;        // 0..7
    const int ej = tidg & 31;        // 0..31

    for (int t = 0; t < T_; ++t) {
        const float* hin = (t == 0) ? h0 : (const float*)g_h[t & 1];
        float* hout      = g_h[(t + 1) & 1];

        // prefetch pre-activation (DRAM/L2 latency overlapped with reload+kloop)
        float pre = __ldcg(hs + ((size_t)(b0 + eb) * T_ + t) * NH_ + j0g + ej);

        // ---- reload h as duplicated pairs: hTd[k][rb*2{,+1}] = h[rb][k] ----
#pragma unroll
        for (int q = 0; q < 4; ++q) {
            int k = (rrow + q * 32) * 4;
            float4 v = __ldcg((const float4*)(hin + (size_t)(b0 + rb) * NH_ + k));
            *(float2*)&hTd[(k + 0) * 16 + rb * 2] = make_float2(v.x, v.x);
            *(float2*)&hTd[(k + 1) * 16 + rb * 2] = make_float2(v.y, v.y);
            *(float2*)&hTd[(k + 2) * 16 + rb * 2] = make_float2(v.z, v.z);
            *(float2*)&hTd[(k + 3) * 16 + rb * 2] = make_float2(v.w, v.w);
        }
        bar_group(gid);

        // ---- FFMA2 k-loop: 4 FFMA2 + 2 LDS.128 per k ----
        unsigned long long acc[2][2];
        acc[0][0] = acc[0][1] = acc[1][0] = acc[1][1] = 0ull;

#pragma unroll 8
        for (int k = kw0; k < kw0 + 64; ++k) {
            ulonglong2 a2 = *(const ulonglong2*)&hTd[k * 16 + bg * 4]; // (b0,b0),(b1,b1)
            ulonglong2 w  = *(const ulonglong2*)&whT[k * 32 + jg * 4]; // (j0,j1),(j2,j3)
            ffma2(acc[0][0], a2.x, w.x); ffma2(acc[0][1], a2.x, w.y);
            ffma2(acc[1][0], a2.y, w.x); ffma2(acc[1][1], a2.y, w.y);
        }

        // ---- stash partials ----
#pragma unroll
        for (int i = 0; i < 2; i++) {
            *(unsigned long long*)&red[widg * 256 + (bg * 2 + i) * 32 + jg * 4]     = acc[i][0];
            *(unsigned long long*)&red[widg * 256 + (bg * 2 + i) * 32 + jg * 4 + 2] = acc[i][1];
        }
        bar_group(gid);

        // ---- reduce 8 warps + pre, tanh, publish ----
        {
            float s = pre;
#pragma unroll
            for (int w = 0; w < 8; w++) s += red[w * 256 + tidg];
            float hv = tanhf(s);
            hs[((size_t)(b0 + eb) * T_ + t) * NH_ + j0g + ej] = hv;
            hout[(size_t)(b0 + eb) * NH_ + j0g + ej] = hv;
        }

        domain_sync(bt, gid, tidg);
    }

    // ---- join both groups of all 16 CTAs of this bt before the tail ----
    __syncthreads();
    if (tid == 0) {
        __threadfence();
        volatile unsigned* genp = &g_fin_gen[bt][0];
        unsigned gen = *genp;
        unsigned c = atomicAdd(&g_fin_cnt[bt][0], 1u);
        if (c == DOM_SZ - 1) {
            g_fin_cnt[bt][0] = 0;
            __threadfence();
            atomicExch(&g_fin_gen[bt][0], gen + 1);
        } else {
            while (*genp == gen) { __nanosleep(32); }
        }
    }
    __syncthreads();

    // =======================================================================
    // Tail: y = hs @ Wy^T, slice (b: bt*16..+16, y: jt*16..+16), 512 threads.
    // hsS[k][m] 64x65, wyS[k][yy] 64x20. Thread: 1 row x 2 cols.
    // =======================================================================
    {
        float* hsS = sm;             // 64 x 65
        float* wyS = sm + 64 * 65;   // 64 x 20
        const int b0t = bt * 16;
        const int y0  = jt * 16;
        const int m   = tid & 63;
        const int cg  = tid >> 6;    // 0..7 -> cols cg*2

        const int wyy = tid & 15;
        const int wkq = ((tid >> 4) & 15) * 4;

        for (int mt = 0; mt < 256; ++mt) {
            float a0 = 0.f, a1 = 0.f;

            for (int kb = 0; kb < 8; ++kb) {
                // hs tile 64 rows x 64 k, transposed into hsS[k][m]
#pragma unroll
                for (int q = 0; q < 2; ++q) {
                    int idx = tid + q * 512;          // 0..1023
                    int mm = idx >> 4;
                    int kq = (idx & 15) * 4;
                    int r  = mt * 64 + mm;
                    const float* src = hs + ((size_t)(b0t + (r >> 10)) * T_ + (r & 1023)) * NH_
                                          + kb * 64 + kq;
                    float4 v = __ldcg((const float4*)src);
                    hsS[(kq + 0) * 65 + mm] = v.x;
                    hsS[(kq + 1) * 65 + mm] = v.y;
                    hsS[(kq + 2) * 65 + mm] = v.z;
                    hsS[(kq + 3) * 65 + mm] = v.w;
                }
                // Wy tile: 16 y x 64 k into wyS[k][yy]
                if (tid < 256) {
                    float4 v = *(const float4*)(Wy + (size_t)(y0 + wyy) * NH_ + kb * 64 + wkq);
                    wyS[(wkq + 0) * 20 + wyy] = v.x;
                    wyS[(wkq + 1) * 20 + wyy] = v.y;
                    wyS[(wkq + 2) * 20 + wyy] = v.z;
                    wyS[(wkq + 3) * 20 + wyy] = v.w;
                }
                __syncthreads();

#pragma unroll 16
                for (int k = 0; k < 64; ++k) {
                    float a = hsS[k * 65 + m];
                    float2 w = *(const float2*)&wyS[k * 20 + cg * 2];
                    a0 = fmaf(a, w.x, a0);
                    a1 = fmaf(a, w.y, a1);
                }
                __syncthreads();
            }

            int r = mt * 64 + m;
            *(float2*)(y + ((size_t)(b0t + (r >> 10)) * T_ + (r & 1023)) * NY_ + y0 + cg * 2)
                = make_float2(a0, a1);
        }
    }
}

// ---------------------------------------------------------------------------
// Launch: [sgemm(pre), rnn_fused2]. Last launch -> ncu captures rnn_fused2.
// ---------------------------------------------------------------------------
extern "C" void kernel_launch(void* const* d_in, const int* in_sizes, int n_in,
                              void* d_out, int out_size)
{
    const float* x  = (const float*)d_in[0];
    const float* h0 = (const float*)d_in[1];
    const float* Wi = (const float*)d_in[2];
    const float* Wh = (const float*)d_in[3];
    const float* Wy = (const float*)d_in[4];

    float* y  = (float*)d_out;
    float* hs = y + (size_t)B_ * T_ * NY_;

    // Phase 1: pre = x @ Wi^T -> hs region (scratch)
    {
        dim3 grid(NH_ / 64, (B_ * T_) / 128);
        sgemm_nt<128, 64, 16, 8, 4, 256><<<grid, 256>>>(x, Wi, hs, B_ * T_, NH_, NX_);
    }
    // Phase 2+3 fused: two overlapped recurrence groups + y GEMM tail
    {
        cudaFuncSetAttribute(rnn_fused2,
                             cudaFuncAttributeMaxDynamicSharedMemorySize, SMEM_BYTES);
        rnn_fused2<<<128, NTHR, SMEM_BYTES>>>(Wh, h0, Wy, hs, y);
    }
}

// round 8
// speedup vs baseline: 1.6555x; 1.6555x over previous
#include <cuda_runtime.h>
#include <math.h>
#include <stdint.h>

#define B_  128
#define T_  1024
#define NX_ 256
#define NH_ 512
#define NY_ 256

// Domain barriers (16 CTAs sharing bt). 128B padded.
__device__ unsigned g_cnt[8][32];
__device__ unsigned g_gen[8][32];

// ---------------------------------------------------------------------------
// Generic NT SGEMM (proven): C[m][n] = sum_k A[m][k] * B[n][k]
// ---------------------------------------------------------------------------
template <int BM, int BN, int BK, int TM, int TN, int NT>
__global__ __launch_bounds__(NT) void sgemm_nt(
    const float* __restrict__ A,
    const float* __restrict__ Bm,
    float* __restrict__ C,
    int M, int N, int K)
{
    __shared__ float As[BK][BM];
    __shared__ float Bs[BK][BN];

    const int tid = threadIdx.x;
    const int m0 = blockIdx.y * BM;
    const int n0 = blockIdx.x * BN;
    const int tx = tid % (BN / TN);
    const int ty = tid / (BN / TN);

    float acc[TM][TN];
#pragma unroll
    for (int i = 0; i < TM; i++)
#pragma unroll
        for (int j = 0; j < TN; j++) acc[i][j] = 0.0f;

    for (int k0 = 0; k0 < K; k0 += BK) {
#pragma unroll
        for (int i = tid; i < BM * (BK / 4); i += NT) {
            int m = i / (BK / 4);
            int kq = (i % (BK / 4)) * 4;
            float4 v = *(const float4*)(A + (long)(m0 + m) * K + k0 + kq);
            As[kq + 0][m] = v.x;
            As[kq + 1][m] = v.y;
            As[kq + 2][m] = v.z;
            As[kq + 3][m] = v.w;
        }
#pragma unroll
        for (int i = tid; i < BN * (BK / 4); i += NT) {
            int n = i / (BK / 4);
            int kq = (i % (BK / 4)) * 4;
            float4 v = *(const float4*)(Bm + (long)(n0 + n) * K + k0 + kq);
            Bs[kq + 0][n] = v.x;
            Bs[kq + 1][n] = v.y;
            Bs[kq + 2][n] = v.z;
            Bs[kq + 3][n] = v.w;
        }
        __syncthreads();

#pragma unroll
        for (int k = 0; k < BK; ++k) {
            float a[TM], b[TN];
#pragma unroll
            for (int i = 0; i < TM; i++) a[i] = As[k][ty * TM + i];
#pragma unroll
            for (int j = 0; j < TN; j++) b[j] = Bs[k][tx * TN + j];
#pragma unroll
            for (int i = 0; i < TM; i++)
#pragma unroll
                for (int j = 0; j < TN; j++) acc[i][j] = fmaf(a[i], b[j], acc[i][j]);
        }
        __syncthreads();
    }

#pragma unroll
    for (int i = 0; i < TM; i++) {
        float4 v = make_float4(acc[i][0], acc[i][1], acc[i][2], acc[i][3]);
        *(float4*)(C + (long)(m0 + ty * TM + i) * N + n0 + tx * TN) = v;
    }
}

// ---------------------------------------------------------------------------
// FFMA2 helper: d += a * b (packed f32x2)
// ---------------------------------------------------------------------------
__device__ __forceinline__ void ffma2(unsigned long long& d,
                                      unsigned long long a, unsigned long long b)
{
    asm("fma.rn.f32x2 %0, %1, %2, %0;" : "+l"(d) : "l"(a), "l"(b));
}
__device__ __forceinline__ void unpack2(unsigned long long v, float& lo, float& hi)
{
    asm("mov.b64 {%0, %1}, %2;" : "=f"(lo), "=f"(hi) : "l"(v));
}

// ---------------------------------------------------------------------------
// Sequential recurrence, register-resident Wh + broadcast-LDS k-loop.
//
// Grid = 128 CTAs = 8 bt x 16 jt. 256 threads = 8 warps (k-split 64 each).
// Lane = output column j (32 per CTA). Each lane holds Wh[j][kw0..kw0+64)
// in 32 packed u64 registers, loaded once, resident for all 1024 steps.
// h round-trips through hs (written at t-1, reloaded at t). SIMD along k:
// acc2[b] += (h[b][2k],h[b][2k+1]) * W2  -> per LDS.128 (uniform address,
// broadcast, 1 wavefront) 2 FFMA2. Cross-warp reduce via red[w][b][j] (u64).
// Sync: 16-CTA domain (bt) count/gen barrier (proven R6/R7 pattern).
// ---------------------------------------------------------------------------
#define NTHR   256
#define DOM_SZ 16

#define SMEM_BYTES 65536   // hT 16x512 f32 (32KB) + red 8x16x32 u64 (32KB)

__device__ __forceinline__ void domain_sync(int bt)
{
    __threadfence();
    __syncthreads();
    if (threadIdx.x == 0) {
        volatile unsigned* genp = &g_gen[bt][0];
        unsigned gen = *genp;
        unsigned c = atomicAdd(&g_cnt[bt][0], 1u);
        if (c == DOM_SZ - 1) {
            g_cnt[bt][0] = 0;
            __threadfence();
            atomicExch(&g_gen[bt][0], gen + 1);
        } else {
            while (*genp == gen) { __nanosleep(32); }
        }
    }
    __syncthreads();
}

__global__ __launch_bounds__(NTHR, 1) void rnn_seq3(
    const float* __restrict__ Wh,   // [NH][NH]
    const float* __restrict__ h0,   // [B][NH]
    float* __restrict__ hs)         // [B][T][NH]: pre in, h out (in place)
{
    extern __shared__ float sm[];
    float* hT = sm;                                              // [16][512]
    unsigned long long* red = (unsigned long long*)(sm + 8192);  // [8][16][32]

    const int tid  = threadIdx.x;
    const int wid  = tid >> 5;
    const int lane = tid & 31;

    const int jt  = blockIdx.x & 15;
    const int bt  = blockIdx.x >> 4;
    const int j0g = jt * 32;
    const int b0  = bt * 16;
    const int kw0 = wid * 64;

    // ---- Wh slice into registers: W[q] = (Wh[j][kw0+2q], Wh[j][kw0+2q+1]) ----
    unsigned long long W[32];
#pragma unroll
    for (int q = 0; q < 16; ++q) {
        ulonglong2 v = *(const ulonglong2*)(Wh + (size_t)(j0g + lane) * NH_ + kw0 + q * 4);
        W[2 * q]     = v.x;
        W[2 * q + 1] = v.y;
    }

    // epilogue mapping: 2 outputs per thread
    const int b_e0 = tid >> 5;           // 0..7
    const int b_e1 = (tid >> 5) + 8;     // 8..15
    const int j_e  = tid & 31;

    for (int t = 0; t < T_; ++t) {
        // ---- prefetch pre-activations (DRAM latency overlaps reload+kloop) ----
        float pre0 = __ldcg(hs + ((size_t)(b0 + b_e0) * T_ + t) * NH_ + j0g + j_e);
        float pre1 = __ldcg(hs + ((size_t)(b0 + b_e1) * T_ + t) * NH_ + j0g + j_e);

        // ---- reload h rows (plain, coalesced; no transpose, no duplication) ----
#pragma unroll
        for (int q = 0; q < 8; ++q) {
            int i  = tid + q * 256;          // 0..2047
            int b  = i >> 7;                 // 0..15
            int k4 = (i & 127) * 4;          // 0..508
            const float* src = (t == 0)
                ? h0 + (size_t)(b0 + b) * NH_ + k4
                : hs + ((size_t)(b0 + b) * T_ + (t - 1)) * NH_ + k4;
            *(float4*)&hT[b * 512 + k4] = __ldcg((const float4*)src);
        }
        __syncthreads();

        // ---- k-loop: register weights, broadcast h loads, SIMD along k ----
        unsigned long long acc[16];
#pragma unroll
        for (int b = 0; b < 16; ++b) acc[b] = 0ull;

#pragma unroll
        for (int b = 0; b < 16; b += 2) {
            const float* ha = &hT[b * 512 + kw0];
            const float* hb = &hT[(b + 1) * 512 + kw0];
#pragma unroll
            for (int q = 0; q < 16; ++q) {
                ulonglong2 va = *(const ulonglong2*)(ha + q * 4);  // broadcast
                ulonglong2 vb = *(const ulonglong2*)(hb + q * 4);  // broadcast
                ffma2(acc[b],     va.x, W[2 * q]);
                ffma2(acc[b + 1], vb.x, W[2 * q]);
                ffma2(acc[b],     va.y, W[2 * q + 1]);
                ffma2(acc[b + 1], vb.y, W[2 * q + 1]);
            }
        }

        // ---- stash partials: red[wid][b][lane] (u64, conflict-free) ----
#pragma unroll
        for (int b = 0; b < 16; ++b)
            red[(wid * 16 + b) * 32 + lane] = acc[b];
        __syncthreads();

        // ---- reduce 8 warps, fold k-pairs, add pre, tanh, publish to hs ----
        {
            float s0 = pre0, s1 = pre1;
#pragma unroll
            for (int w = 0; w < 8; ++w) {
                float lo, hi;
                unpack2(red[(w * 16 + b_e0) * 32 + j_e], lo, hi);
                s0 += lo + hi;
                unpack2(red[(w * 16 + b_e1) * 32 + j_e], lo, hi);
                s1 += lo + hi;
            }
            float hv0 = tanhf(s0);
            float hv1 = tanhf(s1);
            hs[((size_t)(b0 + b_e0) * T_ + t) * NH_ + j0g + j_e] = hv0;
            hs[((size_t)(b0 + b_e1) * T_ + t) * NH_ + j0g + j_e] = hv1;
        }

        domain_sync(bt);
    }
}

// ---------------------------------------------------------------------------
// Launch: [sgemm(pre), rnn_seq3, sgemm(y)]
// ---------------------------------------------------------------------------
extern "C" void kernel_launch(void* const* d_in, const int* in_sizes, int n_in,
                              void* d_out, int out_size)
{
    const float* x  = (const float*)d_in[0];
    const float* h0 = (const float*)d_in[1];
    const float* Wi = (const float*)d_in[2];
    const float* Wh = (const float*)d_in[3];
    const float* Wy = (const float*)d_in[4];

    float* y  = (float*)d_out;
    float* hs = y + (size_t)B_ * T_ * NY_;

    // Phase 1: pre = x @ Wi^T -> hs region (scratch)
    {
        dim3 grid(NH_ / 64, (B_ * T_) / 128);
        sgemm_nt<128, 64, 16, 8, 4, 256><<<grid, 256>>>(x, Wi, hs, B_ * T_, NH_, NX_);
    }
    // Phase 2: sequential recurrence
    {
        cudaFuncSetAttribute(rnn_seq3,
                             cudaFuncAttributeMaxDynamicSharedMemorySize, SMEM_BYTES);
        rnn_seq3<<<128, NTHR, SMEM_BYTES>>>(Wh, h0, hs);
    }
    // Phase 3: y = hs @ Wy^T
    {
        dim3 grid(NY_ / 64, (B_ * T_) / 128);
        sgemm_nt<128, 64, 16, 8, 4, 256><<<grid, 256>>>(hs, Wy, y, B_ * T_, NY_, NH_);
    }
}